// round 1
// baseline (speedup 1.0000x reference)
#include <cuda_runtime.h>

// GaussianKDE: out[q] = (norm/N) * sum_n exp(-0.5*||f_q - x_n||^2)
//   f = features @ bw   (Q x D), dataset x (N x D), D = 64.
// Factored:  out[q] = (norm/N) * a[q] * sum_n b[n] * exp(f_q . x_n)
//   a[q] = exp(-0.5*||f_q||^2),  b[n] = exp(-0.5*||x_n||^2)

#define DCONST 64
#define QCAP 4096
#define NCAP 50048
#define NSPLIT 8

__device__ float g_f[QCAP * DCONST];   // transformed features
__device__ float g_a[QCAP];            // exp(-0.5*||f||^2)
__device__ float g_b[NCAP];            // exp(-0.5*||x||^2)

// ---------------------------------------------------------------------------
__global__ void zero_out_kernel(float* out, int Q) {
    int i = blockIdx.x * blockDim.x + threadIdx.x;
    if (i < Q) out[i] = 0.0f;
}

// ---------------------------------------------------------------------------
// f = features @ bw ; a[q] = exp(-0.5 * ||f_q||^2). One thread per query row.
__global__ void prep_f_kernel(const float* __restrict__ feat,
                              const float* __restrict__ bw, int Q) {
    __shared__ float bws[DCONST][DCONST];   // bws[k][d]
    int tid = threadIdx.x;                  // 64 threads
    for (int i = tid; i < DCONST * DCONST; i += 64)
        bws[i / DCONST][i % DCONST] = bw[i];
    __syncthreads();

    int q = blockIdx.x * 64 + tid;
    if (q >= Q) return;

    float r[DCONST];
    const float4* fr = (const float4*)(feat + (size_t)q * DCONST);
#pragma unroll
    for (int v = 0; v < DCONST / 4; v++) {
        float4 t = fr[v];
        r[4 * v + 0] = t.x; r[4 * v + 1] = t.y;
        r[4 * v + 2] = t.z; r[4 * v + 3] = t.w;
    }

    float f2 = 0.0f;
#pragma unroll 4
    for (int d = 0; d < DCONST; d++) {
        float acc = 0.0f;
#pragma unroll
        for (int k = 0; k < DCONST; k++)
            acc = fmaf(r[k], bws[k][d], acc);   // broadcast smem read
        g_f[(size_t)q * DCONST + d] = acc;
        f2 = fmaf(acc, acc, f2);
    }
    g_a[q] = __expf(-0.5f * f2);
}

// ---------------------------------------------------------------------------
// b[n] = exp(-0.5 * ||x_n||^2). One thread per dataset row.
__global__ void prep_b_kernel(const float* __restrict__ ds, int N) {
    int n = blockIdx.x * blockDim.x + threadIdx.x;
    if (n >= N) return;
    const float4* r = (const float4*)(ds + (size_t)n * DCONST);
    float x2 = 0.0f;
#pragma unroll
    for (int v = 0; v < DCONST / 4; v++) {
        float4 t = r[v];
        x2 = fmaf(t.x, t.x, x2); x2 = fmaf(t.y, t.y, x2);
        x2 = fmaf(t.z, t.z, x2); x2 = fmaf(t.w, t.w, x2);
    }
    g_b[n] = __expf(-0.5f * x2);
}

// ---------------------------------------------------------------------------
// Main fused kernel: 64(Q) x 64(N) tile per block, 256 threads, 4x4 microtile.
// K = 64 in one pass. Tiles stored transposed (k-major) in smem so the inner
// loop does two conflict-free LDS.128 per 16 FFMA.
__global__ __launch_bounds__(256) void kde_main_kernel(
    const float* __restrict__ ds, const float* __restrict__ norm,
    float* __restrict__ out, int Q, int N) {
    __shared__ float fs[DCONST][64];   // fs[k][q]
    __shared__ float xs[DCONST][64];   // xs[k][n]
    __shared__ float bs[64];

    int tid = threadIdx.x;
    int tx = tid & 15;          // 16 n-threads
    int ty = tid >> 4;          // 16 q-threads
    int q0 = blockIdx.x * 64;

    // Load f tile, transposed into fs[k][q]
    {
        int qq = tid & 63;
        int k0 = (tid >> 6) * 16;
        int q = q0 + qq;
#pragma unroll
        for (int v = 0; v < 4; v++) {
            float4 t = make_float4(0.f, 0.f, 0.f, 0.f);
            if (q < Q) t = *(const float4*)(g_f + (size_t)q * DCONST + k0 + 4 * v);
            fs[k0 + 4 * v + 0][qq] = t.x;
            fs[k0 + 4 * v + 1][qq] = t.y;
            fs[k0 + 4 * v + 2][qq] = t.z;
            fs[k0 + 4 * v + 3][qq] = t.w;
        }
    }

    float rowacc[4] = {0.f, 0.f, 0.f, 0.f};

    int Nup = (N + 63) & ~63;
    int per = ((Nup / 64 + NSPLIT - 1) / NSPLIT) * 64;
    int nstart = blockIdx.y * per;
    int nend = min(nstart + per, Nup);

    for (int nc = nstart; nc < nend; nc += 64) {
        __syncthreads();   // prior K-loop reads of xs/bs done (also covers fs load)
        // Load dataset tile, transposed into xs[k][n]; pad with zeros past N.
        {
            int nn = tid & 63;
            int k0 = (tid >> 6) * 16;
            int n = nc + nn;
#pragma unroll
            for (int v = 0; v < 4; v++) {
                float4 t = make_float4(0.f, 0.f, 0.f, 0.f);
                if (n < N) t = *(const float4*)(ds + (size_t)n * DCONST + k0 + 4 * v);
                xs[k0 + 4 * v + 0][nn] = t.x;
                xs[k0 + 4 * v + 1][nn] = t.y;
                xs[k0 + 4 * v + 2][nn] = t.z;
                xs[k0 + 4 * v + 3][nn] = t.w;
            }
            if (tid < 64) bs[tid] = (nc + tid < N) ? g_b[nc + tid] : 0.0f;
        }
        __syncthreads();

        float acc00 = 0.f, acc01 = 0.f, acc02 = 0.f, acc03 = 0.f;
        float acc10 = 0.f, acc11 = 0.f, acc12 = 0.f, acc13 = 0.f;
        float acc20 = 0.f, acc21 = 0.f, acc22 = 0.f, acc23 = 0.f;
        float acc30 = 0.f, acc31 = 0.f, acc32 = 0.f, acc33 = 0.f;

        const float* fp = &fs[0][ty * 4];
        const float* bp = &xs[0][tx * 4];
#pragma unroll 8
        for (int k = 0; k < DCONST; k++) {
            float4 av = *(const float4*)(fp + 64 * k);
            float4 bv = *(const float4*)(bp + 64 * k);
            acc00 = fmaf(av.x, bv.x, acc00);
            acc01 = fmaf(av.x, bv.y, acc01);
            acc02 = fmaf(av.x, bv.z, acc02);
            acc03 = fmaf(av.x, bv.w, acc03);
            acc10 = fmaf(av.y, bv.x, acc10);
            acc11 = fmaf(av.y, bv.y, acc11);
            acc12 = fmaf(av.y, bv.z, acc12);
            acc13 = fmaf(av.y, bv.w, acc13);
            acc20 = fmaf(av.z, bv.x, acc20);
            acc21 = fmaf(av.z, bv.y, acc21);
            acc22 = fmaf(av.z, bv.z, acc22);
            acc23 = fmaf(av.z, bv.w, acc23);
            acc30 = fmaf(av.w, bv.x, acc30);
            acc31 = fmaf(av.w, bv.y, acc31);
            acc32 = fmaf(av.w, bv.z, acc32);
            acc33 = fmaf(av.w, bv.w, acc33);
        }

        // Epilogue: rowacc[i] += b[n] * exp(s)
        float b0 = bs[tx * 4 + 0];
        float b1 = bs[tx * 4 + 1];
        float b2 = bs[tx * 4 + 2];
        float b3 = bs[tx * 4 + 3];

        rowacc[0] = fmaf(b0, __expf(acc00), rowacc[0]);
        rowacc[0] = fmaf(b1, __expf(acc01), rowacc[0]);
        rowacc[0] = fmaf(b2, __expf(acc02), rowacc[0]);
        rowacc[0] = fmaf(b3, __expf(acc03), rowacc[0]);
        rowacc[1] = fmaf(b0, __expf(acc10), rowacc[1]);
        rowacc[1] = fmaf(b1, __expf(acc11), rowacc[1]);
        rowacc[1] = fmaf(b2, __expf(acc12), rowacc[1]);
        rowacc[1] = fmaf(b3, __expf(acc13), rowacc[1]);
        rowacc[2] = fmaf(b0, __expf(acc20), rowacc[2]);
        rowacc[2] = fmaf(b1, __expf(acc21), rowacc[2]);
        rowacc[2] = fmaf(b2, __expf(acc22), rowacc[2]);
        rowacc[2] = fmaf(b3, __expf(acc23), rowacc[2]);
        rowacc[3] = fmaf(b0, __expf(acc30), rowacc[3]);
        rowacc[3] = fmaf(b1, __expf(acc31), rowacc[3]);
        rowacc[3] = fmaf(b2, __expf(acc32), rowacc[3]);
        rowacc[3] = fmaf(b3, __expf(acc33), rowacc[3]);
    }

    float scale = __ldg(norm) / (float)N;
#pragma unroll
    for (int i = 0; i < 4; i++) {
        int q = q0 + ty * 4 + i;
        if (q < Q)
            atomicAdd(&out[q], rowacc[i] * g_a[q] * scale);
    }
}

// ---------------------------------------------------------------------------
extern "C" void kernel_launch(void* const* d_in, const int* in_sizes, int n_in,
                              void* d_out, int out_size) {
    const float* features = (const float*)d_in[0];  // [Q, 64]
    const float* bw       = (const float*)d_in[1];  // [64, 64]
    const float* dataset  = (const float*)d_in[2];  // [N, 64]
    const float* norm     = (const float*)d_in[3];  // [1]

    int Q = in_sizes[0] / DCONST;
    int N = in_sizes[2] / DCONST;
    float* out = (float*)d_out;

    zero_out_kernel<<<(Q + 255) / 256, 256>>>(out, Q);
    prep_f_kernel<<<(Q + 63) / 64, 64>>>(features, bw, Q);
    prep_b_kernel<<<(N + 255) / 256, 256>>>(dataset, N);

    dim3 grid((Q + 63) / 64, NSPLIT);
    kde_main_kernel<<<grid, 256>>>(dataset, norm, out, Q, N);
}

// round 4
// speedup vs baseline: 2.9265x; 2.9265x over previous
#include <cuda_runtime.h>
#include <cstdint>

// GaussianKDE via legacy mma.sync tf32 (2-pass F split) + fused exp epilogue.
// out[q] = (norm/N) * a[q] * sum_n b[n] * exp(f_q . x_n)
//   f = features @ bw,  a[q] = exp(-0.5||f_q||^2),  b[n] = exp(-0.5||x_n||^2)
// S = F_hi.X_hi + F_lo.X_hi  (= F . X_hi exactly); dropped F.X_lo term is
// zero-mean and independent per n -> averages out across the N-sum.

#define DCONST 64
#define QCAP   4096
#define NCAP   50048        // 391 * 128
#define QTILE  128
#define NTILE  128
#define NCHUNK 37           // 32 q-tiles * 37 = 1184 blocks = 8 waves * 148 SMs
#define XS     68           // padded smem row stride in floats (bank-conflict-free)

#define OFF_FHI 0
#define TILE_B  (128 * XS * 4)          // 34816 bytes per 128x64 padded tile
#define OFF_FLO (OFF_FHI + TILE_B)
#define OFF_X   (OFF_FLO + TILE_B)      // 2 buffers
#define OFF_BS  (OFF_X + 2 * TILE_B)    // bs[2][128] floats
#define OFF_RED (OFF_BS + 1024)         // red[256] floats
#define SMEM_TOTAL (OFF_RED + 1024)

__device__ float g_fhi[QCAP * DCONST];
__device__ float g_flo[QCAP * DCONST];
__device__ float g_a[QCAP];
__device__ float g_xhi[NCAP * DCONST];
__device__ float g_b[NCAP];

// ---------------------------------------------------------------------------
__device__ __forceinline__ uint32_t smem_u32(const void* p) {
    uint32_t a;
    asm("{ .reg .u64 t; cvta.to.shared.u64 t, %1; cvt.u32.u64 %0, t; }"
        : "=r"(a) : "l"(p));
    return a;
}
__device__ __forceinline__ void cp16(uint32_t dst, const void* src) {
    asm volatile("cp.async.cg.shared.global [%0], [%1], 16;"
                 :: "r"(dst), "l"(src) : "memory");
}
__device__ __forceinline__ void mma8(float* d, const uint32_t* a,
                                     uint32_t b0, uint32_t b1) {
    asm volatile("mma.sync.aligned.m16n8k8.row.col.f32.tf32.tf32.f32 "
                 "{%0,%1,%2,%3}, {%4,%5,%6,%7}, {%8,%9}, {%0,%1,%2,%3};"
                 : "+f"(d[0]), "+f"(d[1]), "+f"(d[2]), "+f"(d[3])
                 : "r"(a[0]), "r"(a[1]), "r"(a[2]), "r"(a[3]),
                   "r"(b0), "r"(b1));
}
// tf32 round: destination is a .b32 register in PTX.
__device__ __forceinline__ uint32_t to_tf32_bits(float x) {
    uint32_t r;
    asm("cvt.rna.tf32.f32 %0, %1;" : "=r"(r) : "f"(x));
    return r;
}

// ---------------------------------------------------------------------------
__global__ void zero_out_kernel(float* out, int Q) {
    int i = blockIdx.x * blockDim.x + threadIdx.x;
    if (i < Q) out[i] = 0.0f;
}

// f = features @ bw ; store tf32 hi/lo split and a[q]. 64 threads, 1 row each.
__global__ void prep_f_kernel(const float* __restrict__ feat,
                              const float* __restrict__ bw, int Q) {
    __shared__ float bws[DCONST][DCONST];
    int tid = threadIdx.x;
    for (int i = tid; i < DCONST * DCONST; i += 64)
        bws[i / DCONST][i % DCONST] = bw[i];
    __syncthreads();
    int q = blockIdx.x * 64 + tid;
    if (q >= Q) return;

    float r[DCONST];
    const float4* fr = (const float4*)(feat + (size_t)q * DCONST);
#pragma unroll
    for (int v = 0; v < DCONST / 4; v++) {
        float4 t = fr[v];
        r[4 * v + 0] = t.x; r[4 * v + 1] = t.y;
        r[4 * v + 2] = t.z; r[4 * v + 3] = t.w;
    }
    float f2 = 0.0f;
#pragma unroll 4
    for (int d = 0; d < DCONST; d++) {
        float acc = 0.0f;
#pragma unroll
        for (int k = 0; k < DCONST; k++) acc = fmaf(r[k], bws[k][d], acc);
        float hi = __uint_as_float(to_tf32_bits(acc));
        g_fhi[(size_t)q * DCONST + d] = hi;
        g_flo[(size_t)q * DCONST + d] = __uint_as_float(to_tf32_bits(acc - hi));
        f2 = fmaf(acc, acc, f2);
    }
    g_a[q] = expf(-0.5f * f2);
}

// X_hi = tf32(x); b[n] = exp(-0.5||x||^2); zero-pad rows [N, NCAP).
__global__ void prep_x_kernel(const float* __restrict__ ds, int N) {
    int n = blockIdx.x * blockDim.x + threadIdx.x;
    if (n >= NCAP) return;
    if (n < N) {
        float x2 = 0.0f;
        const float4* r = (const float4*)(ds + (size_t)n * DCONST);
#pragma unroll
        for (int v = 0; v < DCONST / 4; v++) {
            float4 t = r[v];
            float e[4] = {t.x, t.y, t.z, t.w};
#pragma unroll
            for (int j = 0; j < 4; j++) {
                g_xhi[(size_t)n * DCONST + 4 * v + j] =
                    __uint_as_float(to_tf32_bits(e[j]));
                x2 = fmaf(e[j], e[j], x2);
            }
        }
        g_b[n] = expf(-0.5f * x2);
    } else {
#pragma unroll
        for (int v = 0; v < DCONST / 4; v++)
            *(float4*)(g_xhi + (size_t)n * DCONST + 4 * v) = make_float4(0, 0, 0, 0);
        g_b[n] = 0.0f;
    }
}

// ---------------------------------------------------------------------------
// Main kernel: 128(Q) x 128(N) tile per block, 256 threads (8 warps).
// Warp = 32(Q) x 64(N): wq = wid>>1 picks 32 Q-rows, wn = wid&1 picks 64 N-cols.
// A_hi fragments for all 8 k-steps preloaded to registers once per block.
__global__ __launch_bounds__(256, 1) void kde_mma_kernel(
    const float* __restrict__ norm, float* __restrict__ out,
    int Q, int N, int NT) {
    extern __shared__ char smem[];
    const uint32_t sb = smem_u32(smem);
    const float* fh = (const float*)(smem + OFF_FHI);
    const float* fl = (const float*)(smem + OFF_FLO);
    const int tid = threadIdx.x, lane = tid & 31, wid = tid >> 5;
    const int wq = wid >> 1, wn = wid & 1;
    const int q0 = blockIdx.x * QTILE;
    const int t0 = (blockIdx.y * NT) / NCHUNK;
    const int t1 = ((blockIdx.y + 1) * NT) / NCHUNK;
    const int cnt = t1 - t0;

    // Stage F tiles (hi+lo) and first X tile via cp.async (one group).
#pragma unroll
    for (int i = 0; i < 8; i++) {
        int e = tid + (i << 8);
        int row = e >> 4, c = e & 15;
        cp16(sb + OFF_FHI + row * (XS * 4) + c * 16,
             g_fhi + (size_t)(q0 + row) * DCONST + c * 4);
        cp16(sb + OFF_FLO + row * (XS * 4) + c * 16,
             g_flo + (size_t)(q0 + row) * DCONST + c * 4);
    }
    {
        int n0 = t0 * NTILE;
#pragma unroll
        for (int i = 0; i < 8; i++) {
            int e = tid + (i << 8);
            int row = e >> 4, c = e & 15;
            cp16(sb + OFF_X + row * (XS * 4) + c * 16,
                 g_xhi + (size_t)(n0 + row) * DCONST + c * 4);
        }
        if (tid < 32) cp16(sb + OFF_BS + tid * 16, g_b + n0 + tid * 4);
    }
    asm volatile("cp.async.commit_group;");

    const int rA = wq * 32 + (lane >> 2);
    const int cA = lane & 3;

    uint32_t ah[2][8][4];     // A_hi fragments, all k-steps, kept in registers
    bool a_loaded = false;
    float racc[2][2] = {{0.f, 0.f}, {0.f, 0.f}};

    for (int j = 0; j < cnt; j++) {
        const int b = j & 1;
        if (j + 1 < cnt) {
            // Prefetch next X tile into the other buffer.
            int n0 = (t0 + j + 1) * NTILE;
            int bb = (j + 1) & 1;
#pragma unroll
            for (int i = 0; i < 8; i++) {
                int e = tid + (i << 8);
                int row = e >> 4, c = e & 15;
                cp16(sb + OFF_X + bb * TILE_B + row * (XS * 4) + c * 16,
                     g_xhi + (size_t)(n0 + row) * DCONST + c * 4);
            }
            if (tid < 32) cp16(sb + OFF_BS + bb * 512 + tid * 16, g_b + n0 + tid * 4);
            asm volatile("cp.async.commit_group;");
            asm volatile("cp.async.wait_group 1;");
        } else {
            asm volatile("cp.async.wait_group 0;");
        }
        __syncthreads();

        if (!a_loaded) {    // F tile resident after first wait
            a_loaded = true;
#pragma unroll
            for (int qs = 0; qs < 2; qs++)
#pragma unroll
                for (int kk = 0; kk < 8; kk++) {
                    const float* p = fh + (rA + qs * 16) * XS + kk * 8 + cA;
                    ah[qs][kk][0] = __float_as_uint(p[0]);
                    ah[qs][kk][1] = __float_as_uint(p[8 * XS]);
                    ah[qs][kk][2] = __float_as_uint(p[4]);
                    ah[qs][kk][3] = __float_as_uint(p[8 * XS + 4]);
                }
        }

        const float* xp = (const float*)(smem + OFF_X + b * TILE_B);
        float acc[2][8][4];
#pragma unroll
        for (int qs = 0; qs < 2; qs++)
#pragma unroll
            for (int ns = 0; ns < 8; ns++)
#pragma unroll
                for (int i = 0; i < 4; i++) acc[qs][ns][i] = 0.f;

#pragma unroll
        for (int kk = 0; kk < 8; kk++) {
            uint32_t al[2][4];
#pragma unroll
            for (int qs = 0; qs < 2; qs++) {
                const float* p = fl + (rA + qs * 16) * XS + kk * 8 + cA;
                al[qs][0] = __float_as_uint(p[0]);
                al[qs][1] = __float_as_uint(p[8 * XS]);
                al[qs][2] = __float_as_uint(p[4]);
                al[qs][3] = __float_as_uint(p[8 * XS + 4]);
            }
#pragma unroll
            for (int ns = 0; ns < 8; ns++) {
                const float* pb = xp + (wn * 64 + ns * 8 + (lane >> 2)) * XS + kk * 8 + cA;
                uint32_t b0 = __float_as_uint(pb[0]);
                uint32_t b1 = __float_as_uint(pb[4]);
                mma8(acc[0][ns], ah[0][kk], b0, b1);
                mma8(acc[0][ns], al[0], b0, b1);
                mma8(acc[1][ns], ah[1][kk], b0, b1);
                mma8(acc[1][ns], al[1], b0, b1);
            }
        }

        // Fused epilogue: racc += b[n] * exp(s). Padded rows: s=0, b=0 -> no-op.
        const float* bsp = (const float*)(smem + OFF_BS + b * 512)
                           + wn * 64 + 2 * (lane & 3);
#pragma unroll
        for (int ns = 0; ns < 8; ns++) {
            float2 bv = *(const float2*)(bsp + ns * 8);
            racc[0][0] += bv.x * __expf(acc[0][ns][0]) + bv.y * __expf(acc[0][ns][1]);
            racc[0][1] += bv.x * __expf(acc[0][ns][2]) + bv.y * __expf(acc[0][ns][3]);
            racc[1][0] += bv.x * __expf(acc[1][ns][0]) + bv.y * __expf(acc[1][ns][1]);
            racc[1][1] += bv.x * __expf(acc[1][ns][2]) + bv.y * __expf(acc[1][ns][3]);
        }
        __syncthreads();   // compute done before buffer b is overwritten
    }

    // Reduce across the 4 lanes sharing each output row.
#pragma unroll
    for (int qs = 0; qs < 2; qs++)
#pragma unroll
        for (int h = 0; h < 2; h++) {
            float v = racc[qs][h];
            v += __shfl_xor_sync(0xffffffff, v, 1);
            v += __shfl_xor_sync(0xffffffff, v, 2);
            racc[qs][h] = v;
        }
    float* red = (float*)(smem + OFF_RED);
    if ((lane & 3) == 0) {
        int r = lane >> 2;
#pragma unroll
        for (int qs = 0; qs < 2; qs++)
#pragma unroll
            for (int h = 0; h < 2; h++)
                red[wn * 128 + wq * 32 + qs * 16 + h * 8 + r] = racc[qs][h];
    }
    __syncthreads();
    if (tid < 128) {
        int q = q0 + tid;
        if (q < Q) {
            float s = red[tid] + red[128 + tid];
            atomicAdd(&out[q], s * g_a[q] * (__ldg(norm) / (float)N));
        }
    }
}

// ---------------------------------------------------------------------------
extern "C" void kernel_launch(void* const* d_in, const int* in_sizes, int n_in,
                              void* d_out, int out_size) {
    const float* features = (const float*)d_in[0];
    const float* bw       = (const float*)d_in[1];
    const float* dataset  = (const float*)d_in[2];
    const float* norm     = (const float*)d_in[3];

    int Q = in_sizes[0] / DCONST;
    int N = in_sizes[2] / DCONST;
    int NT = (N + NTILE - 1) / NTILE;
    float* out = (float*)d_out;

    cudaFuncSetAttribute(kde_mma_kernel,
                         cudaFuncAttributeMaxDynamicSharedMemorySize, SMEM_TOTAL);

    zero_out_kernel<<<(Q + 255) / 256, 256>>>(out, Q);
    prep_f_kernel<<<(Q + 63) / 64, 64>>>(features, bw, Q);
    prep_x_kernel<<<(NCAP + 255) / 256, 256>>>(dataset, N);

    dim3 grid((Q + QTILE - 1) / QTILE, NCHUNK);
    kde_mma_kernel<<<grid, 256, SMEM_TOTAL>>>(norm, out, Q, N, NT);
}